// round 1
// baseline (speedup 1.0000x reference)
#include <cuda_runtime.h>
#include <cstdint>

#define NXQ 41
#define NXY (41*41)
#define GQ 68921
#define CHUNK 128
#define NCHUNK 539            /* ceil(68921/128) */
#define NWORDS (NCHUNK*4)     /* 2156 32-voxel mask words */
#define KPICK 4
#define NEGV (-1.0e9f)
#define VTH  (-1.0e8f)
#define NTHREADS 256

__device__ unsigned int g_maskw[NWORDS];

// Build the sphere mask bitfield once per launch, bit-exactly replicating
// np.linalg.norm(grid_xyz) <= 6.0 in float32 (equivalent to ss <= 36.0f).
__global__ void build_mask_kernel(const float* __restrict__ grid_xyz) {
    int g = blockIdx.x * blockDim.x + threadIdx.x;
    bool inside = false;
    if (g < GQ) {
        float x = grid_xyz[3 * g + 0];
        float y = grid_xyz[3 * g + 1];
        float z = grid_xyz[3 * g + 2];
        float ss = __fadd_rn(__fadd_rn(__fmul_rn(x, x), __fmul_rn(y, y)), __fmul_rn(z, z));
        inside = (ss <= 36.0f);
    }
    unsigned int b = __ballot_sync(0xffffffffu, inside);
    if ((threadIdx.x & 31) == 0) {
        int w = g >> 5;
        if (w >= 0 && w < NWORDS) g_maskw[w] = b;
    }
}

__global__ __launch_bounds__(NTHREADS) void peaks_kernel(
    const float* __restrict__ density,
    const float* __restrict__ grid_xyz,
    const float* __restrict__ Rmats,
    const float* __restrict__ tpos,
    const float* __restrict__ node_mask,
    float* __restrict__ out,
    int rows, int C)
{
    __shared__ float s_cmax[NCHUNK];
    __shared__ int   s_carg[NCHUNK];
    __shared__ unsigned int s_mw[NWORDS];
    __shared__ unsigned char s_flag[NCHUNK];
    __shared__ float s_ax[NXQ];
    __shared__ float s_rv[NTHREADS];
    __shared__ int   s_ri[NTHREADS];
    __shared__ int   s_pi[KPICK], s_pj[KPICK], s_pk[KPICK], s_pv[KPICK];
    __shared__ float s_ps[KPICK];

    const int tid  = threadIdx.x;
    const int lane = tid & 31;
    const int warp = tid >> 5;
    const int row  = blockIdx.x;
    const float* __restrict__ d = density + (long long)row * GQ;

    for (int i = tid; i < NWORDS; i += NTHREADS) s_mw[i] = g_maskw[i];
    for (int i = tid; i < NCHUNK; i += NTHREADS) s_flag[i] = 0;
    if (tid < NXQ) s_ax[tid] = grid_xyz[(long long)tid * NXY * 3];   // axis values (same for x/y/z)
    __syncthreads();

    // ---- single streaming pass: per-chunk (max, first-argmax) ----
    for (int cb = warp * 2; cb < NCHUNK; cb += 16) {
#pragma unroll
        for (int u = 0; u < 2; u++) {
            int c = cb + u;
            if (c >= NCHUNK) break;
            int base = c * CHUNK;
            unsigned m0 = s_mw[4 * c + 0], m1 = s_mw[4 * c + 1];
            unsigned m2 = s_mw[4 * c + 2], m3 = s_mw[4 * c + 3];
            float v0 = NEGV, v1 = NEGV, v2 = NEGV, v3 = NEGV;
            if ((m0 >> lane) & 1u) v0 = __ldg(&d[base + lane]);
            if ((m1 >> lane) & 1u) v1 = __ldg(&d[base + 32 + lane]);
            if ((m2 >> lane) & 1u) v2 = __ldg(&d[base + 64 + lane]);
            if ((m3 >> lane) & 1u) v3 = __ldg(&d[base + 96 + lane]);
            float bv = v0; int bi = base + lane;
            if (v1 > bv) { bv = v1; bi = base + 32 + lane; }
            if (v2 > bv) { bv = v2; bi = base + 64 + lane; }
            if (v3 > bv) { bv = v3; bi = base + 96 + lane; }
#pragma unroll
            for (int off = 16; off > 0; off >>= 1) {
                float ov = __shfl_down_sync(0xffffffffu, bv, off);
                int   oi = __shfl_down_sync(0xffffffffu, bi, off);
                if (ov > bv || (ov == bv && oi < bi)) { bv = ov; bi = oi; }
            }
            if (lane == 0) { s_cmax[c] = bv; s_carg[c] = bi; }
        }
    }
    __syncthreads();

    // ---- K sequential picks with NMS ----
    for (int p = 0; p < KPICK; p++) {
        float bv = -3.0e38f; int bi = 0x7FFFFFFF;
        for (int c = tid; c < NCHUNK; c += NTHREADS) {
            float v = s_cmax[c]; int g = s_carg[c];
            if (v > bv || (v == bv && g < bi)) { bv = v; bi = g; }
        }
        s_rv[tid] = bv; s_ri[tid] = bi;
        __syncthreads();
        for (int s = NTHREADS / 2; s > 0; s >>= 1) {
            if (tid < s) {
                float ov = s_rv[tid + s]; int oi = s_ri[tid + s];
                if (ov > s_rv[tid] || (ov == s_rv[tid] && oi < s_ri[tid])) {
                    s_rv[tid] = ov; s_ri[tid] = oi;
                }
            }
            __syncthreads();
        }
        int   pidx = s_ri[0];
        float pval = s_rv[0];
        int   valid = (pval > VTH) ? 1 : 0;
        int pi = pidx / NXY; int rr = pidx - pi * NXY;
        int pj = rr / NXQ;   int pk = rr - pj * NXQ;
        if (tid == 0) { s_pi[p] = pi; s_pj[p] = pj; s_pk[p] = pk; s_ps[p] = pval; s_pv[p] = valid; }

        if (valid && p < KPICK - 1) {
            __syncthreads();   // publish s_p*[p]
            // mark chunks containing suppressed voxels (<=49 short segments)
            if (tid < 49) {
                int di = tid / 7 - 3, dj = tid % 7 - 3;
                int i = pi + di, j = pj + dj;
                if (i >= 0 && i < NXQ && j >= 0 && j < NXQ) {
                    int kmin = pk - 3 < 0 ? 0 : pk - 3;
                    int kmax = pk + 3 > NXQ - 1 ? NXQ - 1 : pk + 3;
                    int ls = i * NXY + j * NXQ + kmin;
                    int le = ls + (kmax - kmin);
                    s_flag[ls / CHUNK] = 1;
                    s_flag[le / CHUNK] = 1;
                }
            }
            __syncthreads();
            // warp-cooperative recompute of flagged chunks (suppression of all picks so far)
            int ilo = pi - 3 < 0 ? 0 : pi - 3, ihi = pi + 3 > NXQ - 1 ? NXQ - 1 : pi + 3;
            int jlo = pj - 3 < 0 ? 0 : pj - 3, jhi = pj + 3 > NXQ - 1 ? NXQ - 1 : pj + 3;
            int klo = pk - 3 < 0 ? 0 : pk - 3, khi = pk + 3 > NXQ - 1 ? NXQ - 1 : pk + 3;
            int cmin = (ilo * NXY + jlo * NXQ + klo) / CHUNK;
            int cmax = (ihi * NXY + jhi * NXQ + khi) / CHUNK;
            for (int c = cmin + warp; c <= cmax; c += 8) {
                if (!s_flag[c]) continue;
                int base = c * CHUNK;
                float bestv = NEGV; int besti = base + lane;
#pragma unroll
                for (int w = 0; w < 4; w++) {
                    int g = base + w * 32 + lane;
                    float v = NEGV;
                    if ((s_mw[4 * c + w] >> lane) & 1u) {
                        v = __ldg(&d[g]);
                        int gi = g / NXY; int grr = g - gi * NXY;
                        int gj = grr / NXQ; int gk = grr - gj * NXQ;
                        for (int q = 0; q <= p; q++) {
                            if (s_pv[q]) {
                                int ai = abs(gi - s_pi[q]);
                                int aj = abs(gj - s_pj[q]);
                                int ak = abs(gk - s_pk[q]);
                                if (ai <= 3 && aj <= 3 && ak <= 3) v = NEGV;
                            }
                        }
                    }
                    if (v > bestv) { bestv = v; besti = g; }
                }
#pragma unroll
                for (int off = 16; off > 0; off >>= 1) {
                    float ov = __shfl_down_sync(0xffffffffu, bestv, off);
                    int   oi = __shfl_down_sync(0xffffffffu, besti, off);
                    if (ov > bestv || (ov == bestv && oi < besti)) { bestv = ov; besti = oi; }
                }
                if (lane == 0) { s_cmax[c] = bestv; s_carg[c] = besti; s_flag[c] = 0; }
            }
        }
        __syncthreads();
    }

    // ---- epilogue: transform + masking, one thread per pick ----
    if (tid < KPICK) {
        int k = tid;
        int n = row / C;
        float m = node_mask[n];
        int v = s_pv[k];
        float x = 0.f, y = 0.f, z = 0.f;
        if (v) { x = s_ax[s_pi[k]]; y = s_ax[s_pj[k]]; z = s_ax[s_pk[k]]; }
        float score = v ? s_ps[k] : NEGV;
        const float* R = Rmats + (long long)n * 9;
        const float* t = tpos + (long long)n * 3;
        float gx = R[0] * x + R[1] * y + R[2] * z + t[0];
        float gy = R[3] * x + R[4] * y + R[5] * z + t[1];
        float gz = R[6] * x + R[7] * y + R[8] * z + t[2];
        long long P  = (long long)rows * KPICK;
        long long rk = (long long)row * KPICK + k;
        out[rk * 3 + 0] = x * m;
        out[rk * 3 + 1] = y * m;
        out[rk * 3 + 2] = z * m;
        out[3 * P + rk * 3 + 0] = gx * m;
        out[3 * P + rk * 3 + 1] = gy * m;
        out[3 * P + rk * 3 + 2] = gz * m;
        out[6 * P + rk] = score * m;
        out[7 * P + rk] = (v && m != 0.0f) ? 1.0f : 0.0f;
    }
}

extern "C" void kernel_launch(void* const* d_in, const int* in_sizes, int n_in,
                              void* d_out, int out_size) {
    // metadata order: density, grid_xyz, sphere_mask, coords_int, Rmats, tpos, node_mask
    const float* density   = (const float*)d_in[0];
    const float* grid_xyz  = (const float*)d_in[1];
    const float* Rmats     = (const float*)d_in[4];
    const float* tpos      = (const float*)d_in[5];
    const float* node_mask = (const float*)d_in[6];
    int rows = in_sizes[0] / GQ;        // B*N*C
    int BN   = in_sizes[6];             // B*N
    int C    = rows / BN;

    build_mask_kernel<<<(NWORDS * 32 + NTHREADS - 1) / NTHREADS, NTHREADS>>>(grid_xyz);
    peaks_kernel<<<rows, NTHREADS>>>(density, grid_xyz, Rmats, tpos, node_mask,
                                     (float*)d_out, rows, C);
}